// round 14
// baseline (speedup 1.0000x reference)
#include <cuda_runtime.h>
#include <cstdint>

// Problem constants (fixed by the dataset)
#define B_    4
#define N_    8192
#define M_    2048
#define K_    32
#define C_    64
#define NBINS 16

#define WARPS   4     // warps per block
#define ROWS_PW 2     // m-rows per warp (sequential) -> 8 rows per block
#define THREADS (WARPS * 32)

#define G_STRIDE 20   // floats per (m,k) record: 16 c-pairs + 2 reff + 2 pad

typedef unsigned long long ull;

__device__ int g_idx_is64;

// Detect whether nn_index buffer is int64 or int32 (values < 8192 => high
// words of int64 all zero; int32 data makes odd words random). Deterministic.
__global__ void detect_idx_dtype_kernel(const int* __restrict__ words) {
    __shared__ int any_nonzero;
    if (threadIdx.x == 0) any_nonzero = 0;
    __syncthreads();
    int local = 0;
    for (int i = threadIdx.x; i < 2048; i += blockDim.x) {
        if (words[2 * i + 1] != 0) local = 1;
    }
    if (local) atomicOr(&any_nonzero, 1);
    __syncthreads();
    if (threadIdx.x == 0) g_idx_is64 = any_nonzero ? 0 : 1;
}

// Packed fp32x2 ops (Blackwell): one instruction, two fp32 lanes.
#define FMA2(d, a, b, c) \
    asm("fma.rn.f32x2 %0, %1, %2, %3;" : "=l"(d) : "l"(a), "l"(b), "l"(c))
#define MUL2(d, a, b) \
    asm("mul.rn.f32x2 %0, %1, %2;" : "=l"(d) : "l"(a), "l"(b))
#define ADD2(d, a, b) \
    asm("add.rn.f32x2 %0, %1, %2;" : "=l"(d) : "l"(a), "l"(b))

__global__ __launch_bounds__(THREADS, 8) void fuzzy_sphere_kernel(
    const float* __restrict__ database,      // (B, N, 3)
    const float* __restrict__ query,         // (B, M, 3)
    const void*  __restrict__ nn_index_raw,  // (B, M, K) int64 or int32
    const float* __restrict__ nn_dist,       // (B, M, K)
    const float* __restrict__ feats,         // (B, N, C)
    const float* __restrict__ fw,            // (NBINS, C, 1)
    float* __restrict__ out)                 // (B, M, C)
{
    __shared__ float sg[WARPS * K_ * G_STRIDE];  // per-warp records, 10 KB

    const int tid  = threadIdx.x;
    const int lane = tid & 31;
    const int wid  = tid >> 5;                 // warp id
    const int t2   = lane * 2;                 // channel pair base
    const int is64 = g_idx_is64;

    // -------- Weight table in registers, pre-split into lerp form ------------
    // w0r[A*2+E] = w[A,E,R=0];  wdr[A*2+E] = w[A,E,1] - w[A,E,0]
    ull w0r[8], wdr[8];
    #pragma unroll
    for (int ae = 0; ae < 8; ae++) {
        const ull w0 = *(const ull*)(fw + (2 * ae + 0) * C_ + t2);
        const ull w1 = *(const ull*)(fw + (2 * ae + 1) * C_ + t2);
        w0r[ae] = w0;
        ADD2(wdr[ae], w1, w0 ^ 0x8000000080000000ULL);   // w1 - w0 (packed neg)
    }

    float* mygd = sg + wid * K_ * G_STRIDE;

    #pragma unroll 1
    for (int r = 0; r < ROWS_PW; r++) {
        const int gm = blockIdx.x * (WARPS * ROWS_PW) + r * WARPS + wid;

        // ---------------- Phase 1: lane = k ----------------------------------
        // Emit 8 combined coefficients c_AE = fa_A * FE_E (duplicated pairs)
        // plus the radius lerp parameter reff.
        int off_reg;
        {
            const int k = lane;
            const int b = gm >> 11;             // gm / M_

            int nidx;
            if (is64) nidx = (int)((const long long*)nn_index_raw)[(size_t)gm * K_ + k];
            else      nidx = ((const int*)nn_index_raw)[(size_t)gm * K_ + k];

            const float d  = nn_dist[(size_t)gm * K_ + k];
            const float qx = query[gm * 3 + 0];
            const float qy = query[gm * 3 + 1];
            const float qz = query[gm * 3 + 2];
            const float* dbp = database + ((size_t)b * N_ + nidx) * 3;
            const float x = dbp[0] - qx;
            const float y = dbp[1] - qy;
            const float z = dbp[2] - qz;

            const float azimuth = atan2f(y, x) + 3.14159265358979323846f;
            float ct = z / (d + 1e-8f);
            ct = fminf(fmaxf(ct, -1.0f), 1.0f);
            const float elevation = acosf(ct);

            const float SC = 0.63661977236758134f;   // 4/(2pi) == 2/pi
            const float ab = azimuth   * SC;
            const float eb = elevation * SC;
            float rb = d / 0.05f;
            rb = fminf(fmaxf(rb, 0.0f), 2.0f - 1e-6f);

            const float afl = floorf(ab), efl = floorf(eb), rfl = floorf(rb);
            const float afr = ab - afl,   efr = eb - efl,   rfr = rb - rfl;
            const float ai = 1.0f - afr;

            const int a0 = ((int)afl) & 3;
            const int ef = (int)efl;             // 0,1,(2 at poles)
            const int rf = (int)rfl;             // 0 or 1

            // Lerp parameters (FE0 = 1-eeff, FE1 = eeff; FR0 = 1-reff, FR1 = reff)
            const float eeff = (ef == 0) ? efr : 1.0f;
            const float reff = (rf == 0) ? rfr : 1.0f;
            const float ei   = 1.0f - eeff;

            // FA[A]: ai at a0, afr at (a0+1)&3, else 0 — no dynamic indexing
            const float fa0 = (a0 == 0) ? ai : ((a0 == 3) ? afr : 0.0f);
            const float fa1 = (a0 == 1) ? ai : ((a0 == 0) ? afr : 0.0f);
            const float fa2 = (a0 == 2) ? ai : ((a0 == 1) ? afr : 0.0f);
            const float fa3 = (a0 == 3) ? ai : ((a0 == 2) ? afr : 0.0f);

            float4* dst = (float4*)(mygd + k * G_STRIDE);
            dst[0] = make_float4(fa0 * ei, fa0 * ei, fa0 * eeff, fa0 * eeff);
            dst[1] = make_float4(fa1 * ei, fa1 * ei, fa1 * eeff, fa1 * eeff);
            dst[2] = make_float4(fa2 * ei, fa2 * ei, fa2 * eeff, fa2 * eeff);
            dst[3] = make_float4(fa3 * ei, fa3 * ei, fa3 * eeff, fa3 * eeff);
            ((float2*)(mygd + k * G_STRIDE + 16))[0] = make_float2(reff, reff);

            off_reg = (b * N_ + nidx) * C_;
        }
        // Warp-internal producer/consumer only — no block barrier needed.
        __syncwarp();

        // ---------------- Phase 2: lerp weights, dot with c_AE ----------------
        ull acc = 0;                          // f32x2 (0,0)

        // 4-deep software pipeline for the gathered feature loads.
        ull nfp[4];
        #pragma unroll
        for (int k = 0; k < 4; k++) {
            const int off = __shfl_sync(0xffffffffu, off_reg, k);
            nfp[k] = *(const ull*)(feats + off + t2);
        }

        #pragma unroll 4
        for (int k = 0; k < K_; k++) {
            const ull nf = nfp[k & 3];
            if (k + 4 < K_) {
                const int off = __shfl_sync(0xffffffffu, off_reg, k + 4);
                nfp[k & 3] = *(const ull*)(feats + off + t2);
            }

            const ulonglong2* gp = (const ulonglong2*)(mygd + k * G_STRIDE);
            const ulonglong2 C0 = gp[0];     // c_00, c_01
            const ulonglong2 C1 = gp[1];     // c_10, c_11
            const ulonglong2 C2 = gp[2];     // c_20, c_21
            const ulonglong2 C3 = gp[3];     // c_30, c_31
            const ull reff = *(const ull*)(mygd + k * G_STRIDE + 16);

            // wr_AE = w0[AE] + reff*wd[AE];  ws = sum_AE c_AE * wr_AE
            ull wr0, wr1, wsA, wsB;
            FMA2(wr0, reff, wdr[0], w0r[0]);
            FMA2(wr1, reff, wdr[1], w0r[1]);
            MUL2(wsA, C0.x, wr0);
            FMA2(wsA, C0.y, wr1, wsA);
            FMA2(wr0, reff, wdr[2], w0r[2]);
            FMA2(wr1, reff, wdr[3], w0r[3]);
            FMA2(wsA, C1.x, wr0, wsA);
            FMA2(wsA, C1.y, wr1, wsA);
            FMA2(wr0, reff, wdr[4], w0r[4]);
            FMA2(wr1, reff, wdr[5], w0r[5]);
            MUL2(wsB, C2.x, wr0);
            FMA2(wsB, C2.y, wr1, wsB);
            FMA2(wr0, reff, wdr[6], w0r[6]);
            FMA2(wr1, reff, wdr[7], w0r[7]);
            FMA2(wsB, C3.x, wr0, wsB);
            FMA2(wsB, C3.y, wr1, wsB);

            ull ws;
            ADD2(ws, wsA, wsB);
            FMA2(acc, nf, ws, acc);
        }

        *(ull*)(out + (size_t)gm * C_ + t2) = acc;
        __syncwarp();   // protect mygd reuse for the next row
    }
}

extern "C" void kernel_launch(void* const* d_in, const int* in_sizes, int n_in,
                              void* d_out, int out_size) {
    const float* database = (const float*)d_in[0];
    const float* query    = (const float*)d_in[1];
    const void*  nn_index = (const void*) d_in[2];
    // d_in[3] = nn_count (unused by the reference einsum)
    const float* nn_dist  = (const float*)d_in[4];
    const float* feats    = (const float*)d_in[5];
    const float* fw       = (const float*)d_in[6];
    float* out = (float*)d_out;

    detect_idx_dtype_kernel<<<1, 256>>>((const int*)nn_index);

    const int blocks = (B_ * M_) / (WARPS * ROWS_PW);   // 1024
    fuzzy_sphere_kernel<<<blocks, THREADS>>>(
        database, query, nn_index, nn_dist, feats, fw, out);
}

// round 15
// speedup vs baseline: 1.0756x; 1.0756x over previous
#include <cuda_runtime.h>
#include <cstdint>

// Problem constants (fixed by the dataset)
#define B_    4
#define N_    8192
#define M_    2048
#define K_    32
#define C_    64
#define NBINS 16

#define MPB     4     // m-rows per block, one warp per row (warp-autonomous)
#define THREADS 128

#define G_STRIDE 20   // floats per (m,k) record: 16 c-pairs + 2 reff + 2 pad

typedef unsigned long long ull;

__device__ int g_idx_is64;

// Detect whether nn_index buffer is int64 or int32 (values < 8192 => high
// words of int64 all zero; int32 data makes odd words random). Deterministic.
__global__ void detect_idx_dtype_kernel(const int* __restrict__ words) {
    __shared__ int any_nonzero;
    if (threadIdx.x == 0) any_nonzero = 0;
    __syncthreads();
    int local = 0;
    for (int i = threadIdx.x; i < 2048; i += blockDim.x) {
        if (words[2 * i + 1] != 0) local = 1;
    }
    if (local) atomicOr(&any_nonzero, 1);
    __syncthreads();
    if (threadIdx.x == 0) g_idx_is64 = any_nonzero ? 0 : 1;
}

// Packed fp32x2 ops (Blackwell): one instruction, two fp32 lanes.
#define FMA2(d, a, b, c) \
    asm("fma.rn.f32x2 %0, %1, %2, %3;" : "=l"(d) : "l"(a), "l"(b), "l"(c))
#define MUL2(d, a, b) \
    asm("mul.rn.f32x2 %0, %1, %2;" : "=l"(d) : "l"(a), "l"(b))
#define ADD2(d, a, b) \
    asm("add.rn.f32x2 %0, %1, %2;" : "=l"(d) : "l"(a), "l"(b))

__global__ __launch_bounds__(THREADS, 7) void fuzzy_sphere_kernel(
    const float* __restrict__ database,      // (B, N, 3)
    const float* __restrict__ query,         // (B, M, 3)
    const void*  __restrict__ nn_index_raw,  // (B, M, K) int64 or int32
    const float* __restrict__ nn_dist,       // (B, M, K)
    const float* __restrict__ feats,         // (B, N, C)
    const float* __restrict__ fw,            // (NBINS, C, 1)
    float* __restrict__ out)                 // (B, M, C)
{
    __shared__ float sg[MPB * K_ * G_STRIDE];  // per-warp records, 10 KB

    const int tid  = threadIdx.x;
    const int lane = tid & 31;
    const int wid  = tid >> 5;                 // warp id == m-row within block
    const int t2   = lane * 2;                 // channel pair base
    const int gm   = blockIdx.x * MPB + wid;   // this warp's flattened row
    const int is64 = g_idx_is64;

    // -------- Weight table in registers, pre-split into lerp form ------------
    // w0r[A*2+E] = w[A,E,R=0];  wdr[A*2+E] = w[A,E,1] - w[A,E,0]
    ull w0r[8], wdr[8];
    #pragma unroll
    for (int ae = 0; ae < 8; ae++) {
        const ull w0 = *(const ull*)(fw + (2 * ae + 0) * C_ + t2);
        const ull w1 = *(const ull*)(fw + (2 * ae + 1) * C_ + t2);
        w0r[ae] = w0;
        ADD2(wdr[ae], w1, w0 ^ 0x8000000080000000ULL);   // w1 - w0 (packed neg)
    }

    float* mygd = sg + wid * K_ * G_STRIDE;

    // ---------------- Phase 1: lane = k --------------------------------------
    // Emit 8 combined coefficients c_AE = fa_A * FE_E (duplicated pairs) plus
    // the radius lerp parameter reff; keep the feature offset in a register.
    int off_reg;
    {
        const int k = lane;
        const int b = gm >> 11;             // gm / M_

        int nidx;
        if (is64) nidx = (int)((const long long*)nn_index_raw)[(size_t)gm * K_ + k];
        else      nidx = ((const int*)nn_index_raw)[(size_t)gm * K_ + k];

        const float d  = nn_dist[(size_t)gm * K_ + k];
        const float qx = query[gm * 3 + 0];
        const float qy = query[gm * 3 + 1];
        const float qz = query[gm * 3 + 2];
        const float* dbp = database + ((size_t)b * N_ + nidx) * 3;
        const float x = dbp[0] - qx;
        const float y = dbp[1] - qy;
        const float z = dbp[2] - qz;

        const float azimuth = atan2f(y, x) + 3.14159265358979323846f;
        float ct = z / (d + 1e-8f);
        ct = fminf(fmaxf(ct, -1.0f), 1.0f);
        const float elevation = acosf(ct);

        const float SC = 0.63661977236758134f;   // 4/(2pi) == 2/pi
        const float ab = azimuth   * SC;
        const float eb = elevation * SC;
        float rb = d / 0.05f;
        rb = fminf(fmaxf(rb, 0.0f), 2.0f - 1e-6f);

        const float afl = floorf(ab), efl = floorf(eb), rfl = floorf(rb);
        const float afr = ab - afl,   efr = eb - efl,   rfr = rb - rfl;
        const float ai = 1.0f - afr;

        const int a0 = ((int)afl) & 3;
        const int ef = (int)efl;             // 0,1,(2 at poles)
        const int rf = (int)rfl;             // 0 or 1

        // Lerp parameters (FE0 = 1-eeff, FE1 = eeff; FR0 = 1-reff, FR1 = reff)
        const float eeff = (ef == 0) ? efr : 1.0f;
        const float reff = (rf == 0) ? rfr : 1.0f;
        const float ei   = 1.0f - eeff;

        // FA[A]: ai at a0, afr at (a0+1)&3, else 0 — no dynamic indexing
        const float fa0 = (a0 == 0) ? ai : ((a0 == 3) ? afr : 0.0f);
        const float fa1 = (a0 == 1) ? ai : ((a0 == 0) ? afr : 0.0f);
        const float fa2 = (a0 == 2) ? ai : ((a0 == 1) ? afr : 0.0f);
        const float fa3 = (a0 == 3) ? ai : ((a0 == 2) ? afr : 0.0f);

        float4* dst = (float4*)(mygd + k * G_STRIDE);
        dst[0] = make_float4(fa0 * ei, fa0 * ei, fa0 * eeff, fa0 * eeff);
        dst[1] = make_float4(fa1 * ei, fa1 * ei, fa1 * eeff, fa1 * eeff);
        dst[2] = make_float4(fa2 * ei, fa2 * ei, fa2 * eeff, fa2 * eeff);
        dst[3] = make_float4(fa3 * ei, fa3 * ei, fa3 * eeff, fa3 * eeff);
        ((float2*)(mygd + k * G_STRIDE + 16))[0] = make_float2(reff, reff);

        off_reg = (b * N_ + nidx) * C_;
    }
    // Warp-internal producer/consumer only — no block barrier needed.
    __syncwarp();

    // ---------------- Phase 2: lerp weights, dot with c_AE -------------------
    ull accA = 0, accB = 0;               // dual f32x2 accumulators (k parity)

    // 8-deep software pipeline: covers the ~250-cycle L2-hit gather latency.
    ull nfp[8];
    #pragma unroll
    for (int k = 0; k < 8; k++) {
        const int off = __shfl_sync(0xffffffffu, off_reg, k);
        nfp[k] = *(const ull*)(feats + off + t2);
    }

    #pragma unroll 8
    for (int k = 0; k < K_; k++) {
        const ull nf = nfp[k & 7];
        if (k + 8 < K_) {
            const int off = __shfl_sync(0xffffffffu, off_reg, k + 8);
            nfp[k & 7] = *(const ull*)(feats + off + t2);
        }

        const ulonglong2* gp = (const ulonglong2*)(mygd + k * G_STRIDE);
        const ulonglong2 C0 = gp[0];     // c_00, c_01
        const ulonglong2 C1 = gp[1];     // c_10, c_11
        const ulonglong2 C2 = gp[2];     // c_20, c_21
        const ulonglong2 C3 = gp[3];     // c_30, c_31
        const ull reff = *(const ull*)(mygd + k * G_STRIDE + 16);

        // wr_AE = w0[AE] + reff*wd[AE];  ws = sum_AE c_AE * wr_AE
        ull wr0, wr1, wr2, wr3, wsA, wsB;
        FMA2(wr0, reff, wdr[0], w0r[0]);
        FMA2(wr1, reff, wdr[1], w0r[1]);
        FMA2(wr2, reff, wdr[2], w0r[2]);
        FMA2(wr3, reff, wdr[3], w0r[3]);
        MUL2(wsA, C0.x, wr0);
        FMA2(wsA, C0.y, wr1, wsA);
        FMA2(wr0, reff, wdr[4], w0r[4]);
        FMA2(wr1, reff, wdr[5], w0r[5]);
        MUL2(wsB, C1.x, wr2);
        FMA2(wsB, C1.y, wr3, wsB);
        FMA2(wr2, reff, wdr[6], w0r[6]);
        FMA2(wr3, reff, wdr[7], w0r[7]);
        FMA2(wsA, C2.x, wr0, wsA);
        FMA2(wsA, C2.y, wr1, wsA);
        FMA2(wsB, C3.x, wr2, wsB);
        FMA2(wsB, C3.y, wr3, wsB);

        ull ws;
        ADD2(ws, wsA, wsB);
        if (k & 1) { FMA2(accB, nf, ws, accB); }
        else       { FMA2(accA, nf, ws, accA); }
    }

    ull acc;
    ADD2(acc, accA, accB);
    *(ull*)(out + (size_t)gm * C_ + t2) = acc;
}

extern "C" void kernel_launch(void* const* d_in, const int* in_sizes, int n_in,
                              void* d_out, int out_size) {
    const float* database = (const float*)d_in[0];
    const float* query    = (const float*)d_in[1];
    const void*  nn_index = (const void*) d_in[2];
    // d_in[3] = nn_count (unused by the reference einsum)
    const float* nn_dist  = (const float*)d_in[4];
    const float* feats    = (const float*)d_in[5];
    const float* fw       = (const float*)d_in[6];
    float* out = (float*)d_out;

    detect_idx_dtype_kernel<<<1, 256>>>((const int*)nn_index);

    const int blocks = (B_ * M_) / MPB;   // 2048
    fuzzy_sphere_kernel<<<blocks, THREADS>>>(
        database, query, nn_index, nn_dist, feats, fw, out);
}

// round 16
// speedup vs baseline: 1.1650x; 1.0831x over previous
#include <cuda_runtime.h>
#include <cstdint>

// Problem constants (fixed by the dataset)
#define B_    4
#define N_    8192
#define M_    2048
#define K_    32
#define C_    64
#define NBINS 16

#define MPB     4     // m-rows per block, one warp per row (warp-autonomous)
#define THREADS 128

#define G_STRIDE 20   // floats per (m,k) record: 16 c-pairs + 2 reff + 2 pad

typedef unsigned long long ull;

__device__ int g_idx_is64;

// Detect whether nn_index buffer is int64 or int32 (values < 8192 => high
// words of int64 all zero; int32 data makes odd words random). Deterministic.
__global__ void detect_idx_dtype_kernel(const int* __restrict__ words) {
    __shared__ int any_nonzero;
    if (threadIdx.x == 0) any_nonzero = 0;
    __syncthreads();
    int local = 0;
    for (int i = threadIdx.x; i < 2048; i += blockDim.x) {
        if (words[2 * i + 1] != 0) local = 1;
    }
    if (local) atomicOr(&any_nonzero, 1);
    __syncthreads();
    if (threadIdx.x == 0) g_idx_is64 = any_nonzero ? 0 : 1;
}

// Packed fp32x2 ops (Blackwell): one instruction, two fp32 lanes.
#define FMA2(d, a, b, c) \
    asm("fma.rn.f32x2 %0, %1, %2, %3;" : "=l"(d) : "l"(a), "l"(b), "l"(c))
#define MUL2(d, a, b) \
    asm("mul.rn.f32x2 %0, %1, %2;" : "=l"(d) : "l"(a), "l"(b))
#define ADD2(d, a, b) \
    asm("add.rn.f32x2 %0, %1, %2;" : "=l"(d) : "l"(a), "l"(b))

__global__ __launch_bounds__(THREADS, 6) void fuzzy_sphere_kernel(
    const float* __restrict__ database,      // (B, N, 3)
    const float* __restrict__ query,         // (B, M, 3)
    const void*  __restrict__ nn_index_raw,  // (B, M, K) int64 or int32
    const float* __restrict__ nn_dist,       // (B, M, K)
    const float* __restrict__ feats,         // (B, N, C)
    const float* __restrict__ fw,            // (NBINS, C, 1)
    float* __restrict__ out)                 // (B, M, C)
{
    __shared__ float sg[MPB * K_ * G_STRIDE];  // per-warp records, 10 KB

    const int tid  = threadIdx.x;
    const int lane = tid & 31;
    const int wid  = tid >> 5;                 // warp id == m-row within block
    const int t2   = lane * 2;                 // channel pair base
    const int gm   = blockIdx.x * MPB + wid;   // this warp's flattened row
    const int is64 = g_idx_is64;

    float* mygd = sg + wid * K_ * G_STRIDE;

    // ---------------- Phase 1: lane = k --------------------------------------
    // Emit 8 combined coefficients c_AE = fa_A * FE_E (duplicated pairs) plus
    // the radius lerp parameter reff; keep the feature offset in a register.
    int off_reg;
    {
        const int k = lane;
        const int b = gm >> 11;             // gm / M_

        int nidx;
        if (is64) nidx = (int)((const long long*)nn_index_raw)[(size_t)gm * K_ + k];
        else      nidx = ((const int*)nn_index_raw)[(size_t)gm * K_ + k];

        const float d  = nn_dist[(size_t)gm * K_ + k];
        const float qx = query[gm * 3 + 0];
        const float qy = query[gm * 3 + 1];
        const float qz = query[gm * 3 + 2];
        const float* dbp = database + ((size_t)b * N_ + nidx) * 3;
        const float x = dbp[0] - qx;
        const float y = dbp[1] - qy;
        const float z = dbp[2] - qz;

        const float azimuth = atan2f(y, x) + 3.14159265358979323846f;
        float ct = z / (d + 1e-8f);
        ct = fminf(fmaxf(ct, -1.0f), 1.0f);
        const float elevation = acosf(ct);

        const float SC = 0.63661977236758134f;   // 4/(2pi) == 2/pi
        const float ab = azimuth   * SC;
        const float eb = elevation * SC;
        float rb = d / 0.05f;
        rb = fminf(fmaxf(rb, 0.0f), 2.0f - 1e-6f);

        const float afl = floorf(ab), efl = floorf(eb), rfl = floorf(rb);
        const float afr = ab - afl,   efr = eb - efl,   rfr = rb - rfl;
        const float ai = 1.0f - afr;

        const int a0 = ((int)afl) & 3;
        const int ef = (int)efl;             // 0,1,(2 at poles)
        const int rf = (int)rfl;             // 0 or 1

        // Lerp parameters (FE0 = 1-eeff, FE1 = eeff; FR0 = 1-reff, FR1 = reff)
        const float eeff = (ef == 0) ? efr : 1.0f;
        const float reff = (rf == 0) ? rfr : 1.0f;
        const float ei   = 1.0f - eeff;

        // FA[A]: ai at a0, afr at (a0+1)&3, else 0 — no dynamic indexing
        const float fa0 = (a0 == 0) ? ai : ((a0 == 3) ? afr : 0.0f);
        const float fa1 = (a0 == 1) ? ai : ((a0 == 0) ? afr : 0.0f);
        const float fa2 = (a0 == 2) ? ai : ((a0 == 1) ? afr : 0.0f);
        const float fa3 = (a0 == 3) ? ai : ((a0 == 2) ? afr : 0.0f);

        float4* dst = (float4*)(mygd + k * G_STRIDE);
        dst[0] = make_float4(fa0 * ei, fa0 * ei, fa0 * eeff, fa0 * eeff);
        dst[1] = make_float4(fa1 * ei, fa1 * ei, fa1 * eeff, fa1 * eeff);
        dst[2] = make_float4(fa2 * ei, fa2 * ei, fa2 * eeff, fa2 * eeff);
        dst[3] = make_float4(fa3 * ei, fa3 * ei, fa3 * eeff, fa3 * eeff);
        ((float2*)(mygd + k * G_STRIDE + 16))[0] = make_float2(reff, reff);

        off_reg = (b * N_ + nidx) * C_;
    }
    // Warp-internal producer/consumer only — no block barrier needed.
    __syncwarp();

    // ---------------- Phase 2: P/Q accumulation (16 independent chains) ------
    // P[ae] = sum_k c_ae[k]*nf[k];  Q[ae] = sum_k c_ae[k]*(reff[k]*nf[k])
    ull P0 = 0, P1 = 0, P2 = 0, P3 = 0, P4 = 0, P5 = 0, P6 = 0, P7 = 0;
    ull Q0 = 0, Q1 = 0, Q2 = 0, Q3 = 0, Q4 = 0, Q5 = 0, Q6 = 0, Q7 = 0;

    // 4-deep software pipeline for the gathered feature loads.
    ull nfp[4];
    #pragma unroll
    for (int k = 0; k < 4; k++) {
        const int off = __shfl_sync(0xffffffffu, off_reg, k);
        nfp[k] = *(const ull*)(feats + off + t2);
    }

    #pragma unroll 8
    for (int k = 0; k < K_; k++) {
        const ull nf = nfp[k & 3];
        if (k + 4 < K_) {
            const int off = __shfl_sync(0xffffffffu, off_reg, k + 4);
            nfp[k & 3] = *(const ull*)(feats + off + t2);
        }

        const ulonglong2* gp = (const ulonglong2*)(mygd + k * G_STRIDE);
        const ulonglong2 C0 = gp[0];     // c_00, c_01
        const ulonglong2 C1 = gp[1];     // c_10, c_11
        const ulonglong2 C2 = gp[2];     // c_20, c_21
        const ulonglong2 C3 = gp[3];     // c_30, c_31
        const ull reff = *(const ull*)(mygd + k * G_STRIDE + 16);

        ull rnf;
        MUL2(rnf, reff, nf);

        FMA2(P0, C0.x, nf, P0);   FMA2(Q0, C0.x, rnf, Q0);
        FMA2(P1, C0.y, nf, P1);   FMA2(Q1, C0.y, rnf, Q1);
        FMA2(P2, C1.x, nf, P2);   FMA2(Q2, C1.x, rnf, Q2);
        FMA2(P3, C1.y, nf, P3);   FMA2(Q3, C1.y, rnf, Q3);
        FMA2(P4, C2.x, nf, P4);   FMA2(Q4, C2.x, rnf, Q4);
        FMA2(P5, C2.y, nf, P5);   FMA2(Q5, C2.y, rnf, Q5);
        FMA2(P6, C3.x, nf, P6);   FMA2(Q6, C3.x, rnf, Q6);
        FMA2(P7, C3.y, nf, P7);   FMA2(Q7, C3.y, rnf, Q7);
    }

    // ---------------- Epilogue: apply weights once per row -------------------
    // contribution_ae = w0*(P - Q) + w1*Q = w0*P + (w1 - w0)*Q
    const ull SGN = 0x8000000080000000ULL;
    ull acc0 = 0, acc1 = 0;
    ull Ps[8] = {P0, P1, P2, P3, P4, P5, P6, P7};
    ull Qs[8] = {Q0, Q1, Q2, Q3, Q4, Q5, Q6, Q7};
    #pragma unroll
    for (int ae = 0; ae < 8; ae++) {
        const ull w0 = *(const ull*)(fw + (2 * ae + 0) * C_ + t2);
        const ull w1 = *(const ull*)(fw + (2 * ae + 1) * C_ + t2);
        ull wd;
        ADD2(wd, w1, w0 ^ SGN);            // w1 - w0 (packed negate)
        FMA2(acc0, w0, Ps[ae], acc0);
        FMA2(acc1, wd, Qs[ae], acc1);
    }
    ull acc;
    ADD2(acc, acc0, acc1);

    *(ull*)(out + (size_t)gm * C_ + t2) = acc;
}

extern "C" void kernel_launch(void* const* d_in, const int* in_sizes, int n_in,
                              void* d_out, int out_size) {
    const float* database = (const float*)d_in[0];
    const float* query    = (const float*)d_in[1];
    const void*  nn_index = (const void*) d_in[2];
    // d_in[3] = nn_count (unused by the reference einsum)
    const float* nn_dist  = (const float*)d_in[4];
    const float* feats    = (const float*)d_in[5];
    const float* fw       = (const float*)d_in[6];
    float* out = (float*)d_out;

    detect_idx_dtype_kernel<<<1, 256>>>((const int*)nn_index);

    const int blocks = (B_ * M_) / MPB;   // 2048
    fuzzy_sphere_kernel<<<blocks, THREADS>>>(
        database, query, nn_index, nn_dist, feats, fw, out);
}